// round 1
// baseline (speedup 1.0000x reference)
#include <cuda_runtime.h>

// Problem constants
#define BB 2
#define HH 8
#define QQ 4096
#define DD 32
#define GHH 32
#define GWW 32
#define KK 1024          // GH*GW keys per (b,h)
#define QB 64            // queries per block
#define NWARP 16
#define NTHREADS 512

// ---- packed f32x2 helpers (Blackwell) ----
__device__ __forceinline__ void fma2(unsigned long long& a,
                                     unsigned long long x,
                                     unsigned long long y) {
    asm("fma.rn.f32x2 %0, %1, %2, %3;" : "=l"(a) : "l"(x), "l"(y), "l"(a));
}
__device__ __forceinline__ unsigned long long pk2(float lo, float hi) {
    unsigned long long r;
    asm("mov.b64 %0, {%1, %2};" : "=l"(r) : "f"(lo), "f"(hi));
    return r;
}
__device__ __forceinline__ float2 upk2(unsigned long long v) {
    float2 r;
    asm("mov.b64 {%0, %1}, %2;" : "=f"(r.x), "=f"(r.y) : "l"(v));
    return r;
}

__global__ __launch_bounds__(NTHREADS, 1)
void rga_kernel(const float* __restrict__ queries,
                const float* __restrict__ keys,
                const int*   __restrict__ pos,
                const float* __restrict__ rel_bias,
                float*       __restrict__ out)
{
    const int bh  = blockIdx.y;            // 0..15
    const int b   = bh >> 3;
    const int h   = bh & 7;
    const int q0  = blockIdx.x * QB;       // first query of this block
    const int tid = threadIdx.x;
    const int w   = tid >> 5;              // warp 0..15
    const int l   = tid & 31;              // lane

    __shared__ float4 qd2[QB][DD / 2];     // 16 KB: (qd,qd,qd+1,qd+1), pre-scaled
    __shared__ float  bias_sh[63 * 63];    // 15.5 KB: this head's bias table
    __shared__ int2   pos_sh[QB];          // (pos_y, pos_x) per query
    __shared__ float  red[4][NWARP];       // per-warp partial sums, 4 queries/group

    // ---- stage bias slice for this head ----
    {
        const float* bsrc = rel_bias + (size_t)h * 63 * 63;
        for (int i = tid; i < 63 * 63; i += NTHREADS) bias_sh[i] = bsrc[i];
    }
    // ---- stage positions ----
    for (int i = tid; i < QB; i += NTHREADS) {
        pos_sh[i] = ((const int2*)pos)[(size_t)b * QQ + q0 + i];
    }
    // ---- stage queries: scaled, pair-duplicated for f32x2 ----
    {
        const float scale = 0.17677669529663687f;   // 1/sqrt(32)
        const float* qsrc = queries + ((size_t)bh * QQ + q0) * DD;
        for (int i = tid; i < QB * (DD / 2); i += NTHREADS) {
            int qq = i >> 4;            // / 16
            int dp = i & 15;            // % 16
            float a = qsrc[qq * DD + 2 * dp]     * scale;
            float c = qsrc[qq * DD + 2 * dp + 1] * scale;
            qd2[qq][dp] = make_float4(a, a, c, c);
        }
    }

    // ---- load this lane's 2 key rows into registers, interleaved as (k0[d],k1[d]) ----
    const int k0 = w * 64 + 2 * l;                 // first of lane's two keys
    unsigned long long kk[DD];                     // 32 x b64 = 64 regs
    {
        const float4* krow0 = (const float4*)(keys + ((size_t)bh * KK + k0)     * DD);
        const float4* krow1 = (const float4*)(keys + ((size_t)bh * KK + k0 + 1) * DD);
#pragma unroll
        for (int d4 = 0; d4 < 8; d4++) {
            float4 a  = krow0[d4];
            float4 c  = krow1[d4];
            kk[d4 * 4 + 0] = pk2(a.x, c.x);
            kk[d4 * 4 + 1] = pk2(a.y, c.y);
            kk[d4 * 4 + 2] = pk2(a.z, c.z);
            kk[d4 * 4 + 3] = pk2(a.w, c.w);
        }
    }
    __syncthreads();

    const int i_row = k0 >> 5;                     // grid row of both keys
    const int j0    = k0 & 31;                     // grid col of key0 (key1 = j0+1)
    float* outbase  = out + ((size_t)bh * QQ + q0) * KK + k0;

    // ---- main loop: 16 groups of 4 queries ----
    for (int g = 0; g < QB; g += 4) {
        unsigned long long acc[4] = {0ull, 0ull, 0ull, 0ull};

#pragma unroll
        for (int dp = 0; dp < 16; dp++) {
            ulonglong2 u0 = *reinterpret_cast<const ulonglong2*>(&qd2[g + 0][dp]);
            ulonglong2 u1 = *reinterpret_cast<const ulonglong2*>(&qd2[g + 1][dp]);
            ulonglong2 u2 = *reinterpret_cast<const ulonglong2*>(&qd2[g + 2][dp]);
            ulonglong2 u3 = *reinterpret_cast<const ulonglong2*>(&qd2[g + 3][dp]);
            fma2(acc[0], u0.x, kk[2 * dp]);  fma2(acc[0], u0.y, kk[2 * dp + 1]);
            fma2(acc[1], u1.x, kk[2 * dp]);  fma2(acc[1], u1.y, kk[2 * dp + 1]);
            fma2(acc[2], u2.x, kk[2 * dp]);  fma2(acc[2], u2.y, kk[2 * dp + 1]);
            fma2(acc[3], u3.x, kk[2 * dp]);  fma2(acc[3], u3.y, kk[2 * dp + 1]);
        }

        // ---- epilogue: bias + exp + row-sum (no max-shift needed; logits bounded) ----
#pragma unroll
        for (int i = 0; i < 4; i++) {
            float2 s = upk2(acc[i]);
            int2 p   = pos_sh[g + i];
            int base = (i_row + 31 - p.x) * 63 + (j0 + 31 - p.y);
            s.x += bias_sh[base];
            s.y += bias_sh[base + 1];
            float e0 = __expf(s.x);
            float e1 = __expf(s.y);
            acc[i] = pk2(e0, e1);                   // stash exp values for store
            float part = e0 + e1;
#pragma unroll
            for (int o = 16; o; o >>= 1)
                part += __shfl_xor_sync(0xFFFFFFFFu, part, o);
            if (l == 0) red[i][w] = part;
        }
        __syncthreads();

#pragma unroll
        for (int i = 0; i < 4; i++) {
            const float4* rp = (const float4*)red[i];
            float4 r0 = rp[0], r1 = rp[1], r2 = rp[2], r3 = rp[3];
            float tot = ((r0.x + r0.y) + (r0.z + r0.w))
                      + ((r1.x + r1.y) + (r1.z + r1.w))
                      + ((r2.x + r2.y) + (r2.z + r2.w))
                      + ((r3.x + r3.y) + (r3.z + r3.w));
            float rv  = __fdividef(1.0f, tot);
            float2 e  = upk2(acc[i]);
            *(float2*)(outbase + (size_t)(g + i) * KK) = make_float2(e.x * rv, e.y * rv);
        }
        __syncthreads();   // red[] reused next group
    }
}

extern "C" void kernel_launch(void* const* d_in, const int* in_sizes, int n_in,
                              void* d_out, int out_size)
{
    const float* queries  = (const float*)d_in[0];
    const float* keys     = (const float*)d_in[1];
    const int*   pos      = (const int*)  d_in[2];
    const float* rel_bias = (const float*)d_in[3];
    float*       out      = (float*)d_out;

    dim3 grid(QQ / QB, BB * HH);   // (64, 16)
    dim3 block(NTHREADS);
    rga_kernel<<<grid, block>>>(queries, keys, pos, rel_bias, out);
}

// round 2
// speedup vs baseline: 2.0817x; 2.0817x over previous
#include <cuda_runtime.h>
#include <cuda_bf16.h>

#define BB 2
#define HH 8
#define QQ 4096
#define DD 32
#define KK 1024
#define NBH 16

// Packed key fragments: [bh][Tglob(128)][s(2)][lane(32)] -> uint4 {b0hi,b1hi,b0lo,b1lo}
__device__ uint4 g_kpack[NBH * 128 * 2 * 32];

__device__ __forceinline__ unsigned pack_bf16x2(float lo_elem, float hi_elem) {
    __nv_bfloat162 r = __floats2bfloat162_rn(lo_elem, hi_elem); // .x = low half
    return *reinterpret_cast<unsigned*>(&r);
}

// ---------------- prep: rearrange keys into MMA B-fragment order ----------------
__global__ void prep_kernel(const float* __restrict__ keys) {
    int idx = blockIdx.x * 256 + threadIdx.x;        // 131072 total
    int l  = idx & 31;
    int s  = (idx >> 5) & 1;
    int Tg = (idx >> 6) & 127;
    int bh = idx >> 13;
    int g = l >> 2, t = l & 3;
    int n  = Tg * 8 + g;
    int d0 = s * 16 + t * 2;
    const float* kr = keys + ((size_t)bh * KK + n) * DD;
    float x0 = kr[d0], x1 = kr[d0 + 1], x2 = kr[d0 + 8], x3 = kr[d0 + 9];
    float h0 = __bfloat162float(__float2bfloat16(x0));
    float h1 = __bfloat162float(__float2bfloat16(x1));
    float h2 = __bfloat162float(__float2bfloat16(x2));
    float h3 = __bfloat162float(__float2bfloat16(x3));
    uint4 v;
    v.x = pack_bf16x2(h0, h1);
    v.y = pack_bf16x2(h2, h3);
    v.z = pack_bf16x2(x0 - h0, x1 - h1);
    v.w = pack_bf16x2(x2 - h2, x3 - h3);
    g_kpack[idx] = v;
}

// ---------------- main kernel ----------------
__device__ __forceinline__ void mma16816(float* c, const unsigned* a, unsigned b0, unsigned b1) {
    asm volatile(
        "mma.sync.aligned.m16n8k16.row.col.f32.bf16.bf16.f32 "
        "{%0,%1,%2,%3}, {%4,%5,%6,%7}, {%8,%9}, {%0,%1,%2,%3};"
        : "+f"(c[0]), "+f"(c[1]), "+f"(c[2]), "+f"(c[3])
        : "r"(a[0]), "r"(a[1]), "r"(a[2]), "r"(a[3]), "r"(b0), "r"(b1));
}

__global__ __launch_bounds__(512, 1)
void rga_kernel(const float* __restrict__ queries,
                const int*   __restrict__ pos,
                const float* __restrict__ rel_bias,
                float*       __restrict__ out)
{
    const int bh = blockIdx.y;
    const int b  = bh >> 3;
    const int h  = bh & 7;
    const int q0 = blockIdx.x * 32;      // 32 queries per CTA
    const int tid = threadIdx.x;
    const int w  = tid >> 5;
    const int l  = tid & 31;
    const int qt = w >> 3;               // 0..1  q-tile
    const int nw = w & 7;                // 0..7  n-slice (128 keys)
    const int g  = l >> 2, t = l & 3;
    const int m0 = q0 + qt * 16;
    const int n0 = nw * 128;

    __shared__ float bias_sh[63 * 63];
    __shared__ int2  pos_sh[32];
    __shared__ float red[32][8];

    {
        const float* bsrc = rel_bias + (size_t)h * 63 * 63;
        for (int i = tid; i < 63 * 63; i += 512) bias_sh[i] = bsrc[i];
        if (tid < 32) pos_sh[tid] = ((const int2*)pos)[(size_t)b * QQ + q0 + tid];
    }

    // ---- A fragments: hi/lo bf16 split of scaled queries ----
    unsigned Ahi[2][4], Alo[2][4];
    {
        const float scale = 0.17677669529663687f;   // 1/sqrt(32)
        const float* qr0 = queries + ((size_t)bh * QQ + m0 + g) * DD;
        const float* qr1 = queries + ((size_t)bh * QQ + m0 + g + 8) * DD;
#pragma unroll
        for (int s = 0; s < 2; s++) {
            int d0 = s * 16 + 2 * t;
            float2 p0 = *(const float2*)(qr0 + d0);      // a0
            float2 p1 = *(const float2*)(qr1 + d0);      // a1
            float2 p2 = *(const float2*)(qr0 + d0 + 8);  // a2
            float2 p3 = *(const float2*)(qr1 + d0 + 8);  // a3
            float v[8] = {p0.x * scale, p0.y * scale, p1.x * scale, p1.y * scale,
                          p2.x * scale, p2.y * scale, p3.x * scale, p3.y * scale};
#pragma unroll
            for (int i = 0; i < 4; i++) {
                float h0 = __bfloat162float(__float2bfloat16(v[2 * i]));
                float h1 = __bfloat162float(__float2bfloat16(v[2 * i + 1]));
                Ahi[s][i] = pack_bf16x2(h0, h1);
                Alo[s][i] = pack_bf16x2(v[2 * i] - h0, v[2 * i + 1] - h1);
            }
        }
    }
    __syncthreads();

    // ---- MMA main loop: 16 n-tiles x 2 k-steps x 3 splits ----
    float acc[16][4];
#pragma unroll
    for (int T = 0; T < 16; T++) { acc[T][0] = acc[T][1] = acc[T][2] = acc[T][3] = 0.f; }

    const uint4* kp = g_kpack + ((size_t)bh * 128 + nw * 16) * 2 * 32 + l;
#pragma unroll
    for (int T = 0; T < 16; T++) {
        uint4 k0 = kp[(2 * T)     * 32];
        uint4 k1 = kp[(2 * T + 1) * 32];
        mma16816(acc[T], Ahi[0], k0.x, k0.y);   // hi*hi  s=0
        mma16816(acc[T], Ahi[0], k0.z, k0.w);   // hi*lo
        mma16816(acc[T], Alo[0], k0.x, k0.y);   // lo*hi
        mma16816(acc[T], Ahi[1], k1.x, k1.y);   // s=1
        mma16816(acc[T], Ahi[1], k1.z, k1.w);
        mma16816(acc[T], Alo[1], k1.x, k1.y);
    }

    // ---- epilogue: bias + exp + partial row sums ----
    int2 p0 = pos_sh[qt * 16 + g];
    int2 p1 = pos_sh[qt * 16 + g + 8];
    const float* brow0 = bias_sh + (31 - p0.x) * 63 + (31 - p0.y);
    const float* brow1 = bias_sh + (31 - p1.x) * 63 + (31 - p1.y);
    float rs0 = 0.f, rs1 = 0.f;
#pragma unroll
    for (int T = 0; T < 16; T++) {
        int nl = n0 + 8 * T + 2 * t;
        int i  = nl >> 5, j = nl & 31;
        int o  = i * 63 + j;
        float e0 = __expf(acc[T][0] + brow0[o]);
        float e1 = __expf(acc[T][1] + brow0[o + 1]);
        float e2 = __expf(acc[T][2] + brow1[o]);
        float e3 = __expf(acc[T][3] + brow1[o + 1]);
        acc[T][0] = e0; acc[T][1] = e1; acc[T][2] = e2; acc[T][3] = e3;
        rs0 += e0 + e1;
        rs1 += e2 + e3;
    }
    rs0 += __shfl_xor_sync(0xFFFFFFFFu, rs0, 1);
    rs0 += __shfl_xor_sync(0xFFFFFFFFu, rs0, 2);
    rs1 += __shfl_xor_sync(0xFFFFFFFFu, rs1, 1);
    rs1 += __shfl_xor_sync(0xFFFFFFFFu, rs1, 2);
    if (t == 0) {
        red[qt * 16 + g][nw]     = rs0;
        red[qt * 16 + g + 8][nw] = rs1;
    }
    __syncthreads();

    float s0 = 0.f, s1 = 0.f;
#pragma unroll
    for (int i = 0; i < 8; i++) { s0 += red[qt * 16 + g][i]; s1 += red[qt * 16 + g + 8][i]; }
    float inv0 = __fdividef(1.0f, s0);
    float inv1 = __fdividef(1.0f, s1);

    float* o0 = out + ((size_t)bh * QQ + m0 + g) * KK + n0 + 2 * t;
    float* o1 = out + ((size_t)bh * QQ + m0 + g + 8) * KK + n0 + 2 * t;
#pragma unroll
    for (int T = 0; T < 16; T++) {
        *(float2*)(o0 + 8 * T) = make_float2(acc[T][0] * inv0, acc[T][1] * inv0);
        *(float2*)(o1 + 8 * T) = make_float2(acc[T][2] * inv1, acc[T][3] * inv1);
    }
}

extern "C" void kernel_launch(void* const* d_in, const int* in_sizes, int n_in,
                              void* d_out, int out_size)
{
    const float* queries  = (const float*)d_in[0];
    const float* keys     = (const float*)d_in[1];
    const int*   pos      = (const int*)  d_in[2];
    const float* rel_bias = (const float*)d_in[3];
    float*       out      = (float*)d_out;

    prep_kernel<<<512, 256>>>(keys);
    dim3 grid(QQ / 32, NBH);
    rga_kernel<<<grid, dim3(512)>>>(queries, pos, rel_bias, out);
}